// round 1
// baseline (speedup 1.0000x reference)
#include <cuda_runtime.h>
#include <math.h>

#define T_ 2048
#define H_ 2048
#define F_ 1408
#define E_ 60
#define TOPK_ 4
#define SF_ 5632

// ---- device scratch (no allocations allowed) ----
__device__ float g_S[(size_t)T_ * SF_];            // shared-expert intermediate [T, SF]  (46 MB)
__device__ float g_Hbuf[(size_t)T_ * TOPK_ * F_];  // expert intermediate per pair [8192, F] (46 MB)
__device__ int   g_cnt[E_];
__device__ int   g_base[E_];
__device__ int   g_tok[E_ * T_];
__device__ float g_wt[E_ * T_];
__device__ float g_gate[T_];

__device__ __forceinline__ float siluf(float v) { return v / (1.f + expf(-v)); }

// ============================ init / scan ============================
__global__ void init_kernel() {
    int i = threadIdx.x;
    if (i < E_) g_cnt[i] = 0;
}

__global__ void scan_kernel() {
    if (threadIdx.x == 0) {
        int s = 0;
        for (int e = 0; e < E_; ++e) { g_base[e] = s; s += g_cnt[e]; }
    }
}

// ============================ router ============================
// One block per token: logits = x @ router_w, softmax, top-4 -> expert lists.
// Also computes sigmoid(x @ sh_expert_gate).
__global__ __launch_bounds__(256) void router_kernel(
    const float* __restrict__ X, const float* __restrict__ RW,
    const float* __restrict__ SEG)
{
    int t = blockIdx.x;
    __shared__ float xs[H_];
    __shared__ float part[64][4];
    __shared__ float logits[E_];
    __shared__ float red[256];
    int tid = threadIdx.x;

    for (int i = tid; i < H_; i += 256) xs[i] = X[(size_t)t * H_ + i];
    __syncthreads();

    int e = tid >> 2, q = tid & 3;
    if (e < E_) {
        float s = 0.f;
        int h0 = q * (H_ / 4);
        for (int h = h0; h < h0 + H_ / 4; ++h) s += xs[h] * RW[(size_t)h * E_ + e];
        part[e][q] = s;
    }
    float gsum = 0.f;
    for (int i = tid; i < H_; i += 256) gsum += xs[i] * SEG[i];
    red[tid] = gsum;
    __syncthreads();

    if (e < E_ && q == 0)
        logits[e] = part[e][0] + part[e][1] + part[e][2] + part[e][3];

    for (int st = 128; st > 0; st >>= 1) {
        if (tid < st) red[tid] += red[tid + st];
        __syncthreads();
    }

    if (tid == 0) {
        g_gate[t] = 1.f / (1.f + expf(-red[0]));
        float mx = -1e30f;
        for (int i = 0; i < E_; ++i) mx = fmaxf(mx, logits[i]);
        float sum = 0.f;
        for (int i = 0; i < E_; ++i) { logits[i] = expf(logits[i] - mx); sum += logits[i]; }
        float inv = 1.f / sum;
        for (int k = 0; k < TOPK_; ++k) {
            int bi = 0; float bv = -1.f;
            for (int i = 0; i < E_; ++i)
                if (logits[i] > bv) { bv = logits[i]; bi = i; }
            logits[bi] = -1.f;
            int slot = atomicAdd(&g_cnt[bi], 1);
            g_tok[bi * T_ + slot] = t;
            g_wt[bi * T_ + slot]  = bv * inv;
        }
    }
}

// ============================ shared-expert up/gate ============================
// g_S = silu(X @ Gw) * (X @ Uw).  BM=128 BN=64 TK=16, micro 8x4, dual accumulators.
__global__ __launch_bounds__(256) void shared_upgate_kernel(
    const float* __restrict__ X, const float* __restrict__ Gw,
    const float* __restrict__ Uw)
{
    const int n0 = blockIdx.x * 64;
    const int m0 = blockIdx.y * 128;
    __shared__ float As[2][16][132];
    __shared__ float Bg[2][16][64];
    __shared__ float Bu[2][16][64];
    const int tid = threadIdx.x;
    const int tx = tid & 15;
    const int ty = tid >> 4;
    const int am0 = tid >> 2, akq = (tid & 3) * 4;
    const int bkr = tid >> 4, bnq = (tid & 15) * 4;

    float cg[8][4], cu[8][4];
    #pragma unroll
    for (int i = 0; i < 8; ++i)
        #pragma unroll
        for (int j = 0; j < 4; ++j) { cg[i][j] = 0.f; cu[i][j] = 0.f; }

    const int KT = H_ / 16;
    {
        float4 v = *(const float4*)&X[(size_t)(m0 + am0) * H_ + akq];
        As[0][akq + 0][am0] = v.x; As[0][akq + 1][am0] = v.y;
        As[0][akq + 2][am0] = v.z; As[0][akq + 3][am0] = v.w;
        v = *(const float4*)&X[(size_t)(m0 + am0 + 64) * H_ + akq];
        As[0][akq + 0][am0 + 64] = v.x; As[0][akq + 1][am0 + 64] = v.y;
        As[0][akq + 2][am0 + 64] = v.z; As[0][akq + 3][am0 + 64] = v.w;
        *(float4*)&Bg[0][bkr][bnq] = *(const float4*)&Gw[(size_t)bkr * SF_ + n0 + bnq];
        *(float4*)&Bu[0][bkr][bnq] = *(const float4*)&Uw[(size_t)bkr * SF_ + n0 + bnq];
    }
    __syncthreads();

    float4 ra0, ra1, rbg, rbu;
    for (int kt = 0; kt < KT; ++kt) {
        int cur = kt & 1;
        if (kt + 1 < KT) {
            int k0 = (kt + 1) * 16;
            ra0 = *(const float4*)&X[(size_t)(m0 + am0) * H_ + k0 + akq];
            ra1 = *(const float4*)&X[(size_t)(m0 + am0 + 64) * H_ + k0 + akq];
            rbg = *(const float4*)&Gw[(size_t)(k0 + bkr) * SF_ + n0 + bnq];
            rbu = *(const float4*)&Uw[(size_t)(k0 + bkr) * SF_ + n0 + bnq];
        }
        #pragma unroll 4
        for (int k = 0; k < 16; ++k) {
            float4 a0 = *(const float4*)&As[cur][k][ty * 8];
            float4 a1 = *(const float4*)&As[cur][k][ty * 8 + 4];
            float4 bg = *(const float4*)&Bg[cur][k][tx * 4];
            float4 bu = *(const float4*)&Bu[cur][k][tx * 4];
            float a[8] = {a0.x, a0.y, a0.z, a0.w, a1.x, a1.y, a1.z, a1.w};
            float gg[4] = {bg.x, bg.y, bg.z, bg.w};
            float uu[4] = {bu.x, bu.y, bu.z, bu.w};
            #pragma unroll
            for (int i = 0; i < 8; ++i)
                #pragma unroll
                for (int j = 0; j < 4; ++j) {
                    cg[i][j] += a[i] * gg[j];
                    cu[i][j] += a[i] * uu[j];
                }
        }
        if (kt + 1 < KT) {
            int nb = (kt + 1) & 1;
            As[nb][akq + 0][am0] = ra0.x; As[nb][akq + 1][am0] = ra0.y;
            As[nb][akq + 2][am0] = ra0.z; As[nb][akq + 3][am0] = ra0.w;
            As[nb][akq + 0][am0 + 64] = ra1.x; As[nb][akq + 1][am0 + 64] = ra1.y;
            As[nb][akq + 2][am0 + 64] = ra1.z; As[nb][akq + 3][am0 + 64] = ra1.w;
            *(float4*)&Bg[nb][bkr][bnq] = rbg;
            *(float4*)&Bu[nb][bkr][bnq] = rbu;
        }
        __syncthreads();
    }

    #pragma unroll
    for (int i = 0; i < 8; ++i) {
        int row = m0 + ty * 8 + i;
        float4 o;
        o.x = siluf(cg[i][0]) * cu[i][0];
        o.y = siluf(cg[i][1]) * cu[i][1];
        o.z = siluf(cg[i][2]) * cu[i][2];
        o.w = siluf(cg[i][3]) * cu[i][3];
        *(float4*)&g_S[(size_t)row * SF_ + n0 + tx * 4] = o;
    }
}

// ============================ shared-expert down ============================
// out = sigmoid_gate[t] * (g_S @ Wd).  BM=128 BN=128 TK=8, micro 8x8.
__global__ __launch_bounds__(256) void shared_down_kernel(
    const float* __restrict__ Wd, float* __restrict__ Out)
{
    const int n0 = blockIdx.x * 128;
    const int m0 = blockIdx.y * 128;
    __shared__ float As[2][8][132];
    __shared__ float Bs[2][8][128];
    const int tid = threadIdx.x;
    const int tx = tid & 15;
    const int ty = tid >> 4;
    const int am0 = tid >> 1, akq = (tid & 1) * 4;
    const int bkr = tid >> 5, bnq = (tid & 31) * 4;

    float acc[8][8];
    #pragma unroll
    for (int i = 0; i < 8; ++i)
        #pragma unroll
        for (int j = 0; j < 8; ++j) acc[i][j] = 0.f;

    const int KT = SF_ / 8;
    {
        float4 v = *(const float4*)&g_S[(size_t)(m0 + am0) * SF_ + akq];
        As[0][akq + 0][am0] = v.x; As[0][akq + 1][am0] = v.y;
        As[0][akq + 2][am0] = v.z; As[0][akq + 3][am0] = v.w;
        *(float4*)&Bs[0][bkr][bnq] = *(const float4*)&Wd[(size_t)bkr * H_ + n0 + bnq];
    }
    __syncthreads();

    float4 ra, rb;
    for (int kt = 0; kt < KT; ++kt) {
        int cur = kt & 1;
        if (kt + 1 < KT) {
            int k0 = (kt + 1) * 8;
            ra = *(const float4*)&g_S[(size_t)(m0 + am0) * SF_ + k0 + akq];
            rb = *(const float4*)&Wd[(size_t)(k0 + bkr) * H_ + n0 + bnq];
        }
        #pragma unroll
        for (int k = 0; k < 8; ++k) {
            float4 a0 = *(const float4*)&As[cur][k][ty * 8];
            float4 a1 = *(const float4*)&As[cur][k][ty * 8 + 4];
            float4 b0 = *(const float4*)&Bs[cur][k][tx * 8];
            float4 b1 = *(const float4*)&Bs[cur][k][tx * 8 + 4];
            float a[8] = {a0.x, a0.y, a0.z, a0.w, a1.x, a1.y, a1.z, a1.w};
            float b[8] = {b0.x, b0.y, b0.z, b0.w, b1.x, b1.y, b1.z, b1.w};
            #pragma unroll
            for (int i = 0; i < 8; ++i)
                #pragma unroll
                for (int j = 0; j < 8; ++j) acc[i][j] += a[i] * b[j];
        }
        if (kt + 1 < KT) {
            int nb = (kt + 1) & 1;
            As[nb][akq + 0][am0] = ra.x; As[nb][akq + 1][am0] = ra.y;
            As[nb][akq + 2][am0] = ra.z; As[nb][akq + 3][am0] = ra.w;
            *(float4*)&Bs[nb][bkr][bnq] = rb;
        }
        __syncthreads();
    }

    #pragma unroll
    for (int i = 0; i < 8; ++i) {
        int row = m0 + ty * 8 + i;
        float gt = g_gate[row];
        float4 o0, o1;
        o0.x = gt * acc[i][0]; o0.y = gt * acc[i][1]; o0.z = gt * acc[i][2]; o0.w = gt * acc[i][3];
        o1.x = gt * acc[i][4]; o1.y = gt * acc[i][5]; o1.z = gt * acc[i][6]; o1.w = gt * acc[i][7];
        *(float4*)&Out[(size_t)row * H_ + n0 + tx * 8]     = o0;
        *(float4*)&Out[(size_t)row * H_ + n0 + tx * 8 + 4] = o1;
    }
}

// ============================ expert up/gate (grouped, gather) ============================
// For expert e: Hbuf[pair] = silu(x[tok] @ Wg_e) * (x[tok] @ Wu_e).
// BM=64 BN=128 TK=16, micro 4x8, dual accumulators.
__global__ __launch_bounds__(256) void expert_upgate_kernel(
    const float* __restrict__ X, const float* __restrict__ WG,
    const float* __restrict__ WU)
{
    const int e = blockIdx.z;
    const int cnt = g_cnt[e];
    const int m0 = blockIdx.y * 64;
    if (m0 >= cnt) return;
    const int n0 = blockIdx.x * 128;

    __shared__ int toks[64];
    __shared__ float As[2][16][68];
    __shared__ float Bg[2][16][128];
    __shared__ float Bu[2][16][128];
    const int tid = threadIdx.x;
    const int tx = tid & 15;
    const int ty = tid >> 4;
    const int am0 = tid >> 2, akq = (tid & 3) * 4;

    if (tid < 64) {
        int mm = m0 + tid;
        toks[tid] = g_tok[e * T_ + (mm < cnt ? mm : cnt - 1)];
    }
    __syncthreads();

    const float* Gp = WG + (size_t)e * H_ * F_;
    const float* Up = WU + (size_t)e * H_ * F_;

    float cg[4][8], cu[4][8];
    #pragma unroll
    for (int i = 0; i < 4; ++i)
        #pragma unroll
        for (int j = 0; j < 8; ++j) { cg[i][j] = 0.f; cu[i][j] = 0.f; }

    const int KT = H_ / 16;
    {
        float4 v = *(const float4*)&X[(size_t)toks[am0] * H_ + akq];
        As[0][akq + 0][am0] = v.x; As[0][akq + 1][am0] = v.y;
        As[0][akq + 2][am0] = v.z; As[0][akq + 3][am0] = v.w;
        #pragma unroll
        for (int l = 0; l < 2; ++l) {
            int idx = tid + l * 256;
            int kr = idx >> 5, nq = (idx & 31) * 4;
            *(float4*)&Bg[0][kr][nq] = *(const float4*)&Gp[(size_t)kr * F_ + n0 + nq];
            *(float4*)&Bu[0][kr][nq] = *(const float4*)&Up[(size_t)kr * F_ + n0 + nq];
        }
    }
    __syncthreads();

    float4 ra, rbg0, rbg1, rbu0, rbu1;
    for (int kt = 0; kt < KT; ++kt) {
        int cur = kt & 1;
        if (kt + 1 < KT) {
            int k0 = (kt + 1) * 16;
            ra = *(const float4*)&X[(size_t)toks[am0] * H_ + k0 + akq];
            int kr0 = tid >> 5, nq0 = (tid & 31) * 4;
            int idx1 = tid + 256;
            int kr1 = idx1 >> 5, nq1 = (idx1 & 31) * 4;
            rbg0 = *(const float4*)&Gp[(size_t)(k0 + kr0) * F_ + n0 + nq0];
            rbg1 = *(const float4*)&Gp[(size_t)(k0 + kr1) * F_ + n0 + nq1];
            rbu0 = *(const float4*)&Up[(size_t)(k0 + kr0) * F_ + n0 + nq0];
            rbu1 = *(const float4*)&Up[(size_t)(k0 + kr1) * F_ + n0 + nq1];
        }
        #pragma unroll 4
        for (int k = 0; k < 16; ++k) {
            float4 av = *(const float4*)&As[cur][k][ty * 4];
            float4 bg0 = *(const float4*)&Bg[cur][k][tx * 8];
            float4 bg1 = *(const float4*)&Bg[cur][k][tx * 8 + 4];
            float4 bu0 = *(const float4*)&Bu[cur][k][tx * 8];
            float4 bu1 = *(const float4*)&Bu[cur][k][tx * 8 + 4];
            float a[4] = {av.x, av.y, av.z, av.w};
            float gg[8] = {bg0.x, bg0.y, bg0.z, bg0.w, bg1.x, bg1.y, bg1.z, bg1.w};
            float uu[8] = {bu0.x, bu0.y, bu0.z, bu0.w, bu1.x, bu1.y, bu1.z, bu1.w};
            #pragma unroll
            for (int i = 0; i < 4; ++i)
                #pragma unroll
                for (int j = 0; j < 8; ++j) {
                    cg[i][j] += a[i] * gg[j];
                    cu[i][j] += a[i] * uu[j];
                }
        }
        if (kt + 1 < KT) {
            int nb = (kt + 1) & 1;
            As[nb][akq + 0][am0] = ra.x; As[nb][akq + 1][am0] = ra.y;
            As[nb][akq + 2][am0] = ra.z; As[nb][akq + 3][am0] = ra.w;
            int kr0 = tid >> 5, nq0 = (tid & 31) * 4;
            int idx1 = tid + 256;
            int kr1 = idx1 >> 5, nq1 = (idx1 & 31) * 4;
            *(float4*)&Bg[nb][kr0][nq0] = rbg0;
            *(float4*)&Bg[nb][kr1][nq1] = rbg1;
            *(float4*)&Bu[nb][kr0][nq0] = rbu0;
            *(float4*)&Bu[nb][kr1][nq1] = rbu1;
        }
        __syncthreads();
    }

    const int pbase = g_base[e];
    #pragma unroll
    for (int i = 0; i < 4; ++i) {
        int row = m0 + ty * 4 + i;
        if (row < cnt) {
            size_t pr = (size_t)(pbase + row) * F_;
            float4 o0, o1;
            o0.x = siluf(cg[i][0]) * cu[i][0]; o0.y = siluf(cg[i][1]) * cu[i][1];
            o0.z = siluf(cg[i][2]) * cu[i][2]; o0.w = siluf(cg[i][3]) * cu[i][3];
            o1.x = siluf(cg[i][4]) * cu[i][4]; o1.y = siluf(cg[i][5]) * cu[i][5];
            o1.z = siluf(cg[i][6]) * cu[i][6]; o1.w = siluf(cg[i][7]) * cu[i][7];
            *(float4*)&g_Hbuf[pr + n0 + tx * 8]     = o0;
            *(float4*)&g_Hbuf[pr + n0 + tx * 8 + 4] = o1;
        }
    }
}

// ============================ expert down (grouped, scatter-add) ============================
// out[tok] += w * (Hbuf_pair @ Wd_e).  BM=64 BN=128 TK=16, micro 4x8.
__global__ __launch_bounds__(256) void expert_down_kernel(
    const float* __restrict__ WD, float* __restrict__ Out)
{
    const int e = blockIdx.z;
    const int cnt = g_cnt[e];
    const int m0 = blockIdx.y * 64;
    if (m0 >= cnt) return;
    const int n0 = blockIdx.x * 128;
    const int pbase = g_base[e];

    __shared__ float As[2][16][68];
    __shared__ float Bs[2][16][128];
    const int tid = threadIdx.x;
    const int tx = tid & 15;
    const int ty = tid >> 4;
    const int am0 = tid >> 2, akq = (tid & 3) * 4;
    const int arow = pbase + (m0 + am0 < cnt ? m0 + am0 : cnt - 1);

    const float* Dp = WD + (size_t)e * F_ * H_;

    float acc[4][8];
    #pragma unroll
    for (int i = 0; i < 4; ++i)
        #pragma unroll
        for (int j = 0; j < 8; ++j) acc[i][j] = 0.f;

    const int KT = F_ / 16;
    {
        float4 v = *(const float4*)&g_Hbuf[(size_t)arow * F_ + akq];
        As[0][akq + 0][am0] = v.x; As[0][akq + 1][am0] = v.y;
        As[0][akq + 2][am0] = v.z; As[0][akq + 3][am0] = v.w;
        #pragma unroll
        for (int l = 0; l < 2; ++l) {
            int idx = tid + l * 256;
            int kr = idx >> 5, nq = (idx & 31) * 4;
            *(float4*)&Bs[0][kr][nq] = *(const float4*)&Dp[(size_t)kr * H_ + n0 + nq];
        }
    }
    __syncthreads();

    float4 ra, rb0, rb1;
    for (int kt = 0; kt < KT; ++kt) {
        int cur = kt & 1;
        if (kt + 1 < KT) {
            int k0 = (kt + 1) * 16;
            ra = *(const float4*)&g_Hbuf[(size_t)arow * F_ + k0 + akq];
            int kr0 = tid >> 5, nq0 = (tid & 31) * 4;
            int idx1 = tid + 256;
            int kr1 = idx1 >> 5, nq1 = (idx1 & 31) * 4;
            rb0 = *(const float4*)&Dp[(size_t)(k0 + kr0) * H_ + n0 + nq0];
            rb1 = *(const float4*)&Dp[(size_t)(k0 + kr1) * H_ + n0 + nq1];
        }
        #pragma unroll 4
        for (int k = 0; k < 16; ++k) {
            float4 av = *(const float4*)&As[cur][k][ty * 4];
            float4 b0 = *(const float4*)&Bs[cur][k][tx * 8];
            float4 b1 = *(const float4*)&Bs[cur][k][tx * 8 + 4];
            float a[4] = {av.x, av.y, av.z, av.w};
            float b[8] = {b0.x, b0.y, b0.z, b0.w, b1.x, b1.y, b1.z, b1.w};
            #pragma unroll
            for (int i = 0; i < 4; ++i)
                #pragma unroll
                for (int j = 0; j < 8; ++j) acc[i][j] += a[i] * b[j];
        }
        if (kt + 1 < KT) {
            int nb = (kt + 1) & 1;
            As[nb][akq + 0][am0] = ra.x; As[nb][akq + 1][am0] = ra.y;
            As[nb][akq + 2][am0] = ra.z; As[nb][akq + 3][am0] = ra.w;
            int kr0 = tid >> 5, nq0 = (tid & 31) * 4;
            int idx1 = tid + 256;
            int kr1 = idx1 >> 5, nq1 = (idx1 & 31) * 4;
            *(float4*)&Bs[nb][kr0][nq0] = rb0;
            *(float4*)&Bs[nb][kr1][nq1] = rb1;
        }
        __syncthreads();
    }

    #pragma unroll
    for (int i = 0; i < 4; ++i) {
        int row = m0 + ty * 4 + i;
        if (row < cnt) {
            int tok = g_tok[e * T_ + row];
            float w = g_wt[e * T_ + row];
            float* op = Out + (size_t)tok * H_ + n0 + tx * 8;
            #pragma unroll
            for (int j = 0; j < 8; ++j) atomicAdd(op + j, w * acc[i][j]);
        }
    }
}

// ============================ launch ============================
extern "C" void kernel_launch(void* const* d_in, const int* in_sizes, int n_in,
                              void* d_out, int out_size)
{
    const float* x   = (const float*)d_in[0];
    const float* rw  = (const float*)d_in[1];
    const float* wg  = (const float*)d_in[2];
    const float* wu  = (const float*)d_in[3];
    const float* wd  = (const float*)d_in[4];
    const float* shg = (const float*)d_in[5];
    const float* shu = (const float*)d_in[6];
    const float* shd = (const float*)d_in[7];
    const float* seg = (const float*)d_in[8];
    float* out = (float*)d_out;

    init_kernel<<<1, 64>>>();
    router_kernel<<<T_, 256>>>(x, rw, seg);
    scan_kernel<<<1, 32>>>();

    // shared expert
    shared_upgate_kernel<<<dim3(SF_ / 64, T_ / 128), 256>>>(x, shg, shu);
    shared_down_kernel<<<dim3(H_ / 128, T_ / 128), 256>>>(shd, out);  // writes out

    // routed experts (accumulate into out)
    expert_upgate_kernel<<<dim3(F_ / 128, T_ / 64, E_), 256>>>(x, wg, wu);
    expert_down_kernel<<<dim3(H_ / 128, T_ / 64, E_), 256>>>(wd, out);
}